// round 6
// baseline (speedup 1.0000x reference)
#include <cuda_runtime.h>
#include <math.h>

// ---------------- problem-size scratch (device globals: allocation-free) ----
#define NMAX 100000
#define EMAX 1600000

__device__ float g_xw1[NMAX * 128];   // x @ W1
__device__ float g_h  [NMAX * 128];   // layer-1 output (post agg+bias+relu)
__device__ float g_xw2[NMAX * 64];    // h @ W2
__device__ float g_dinv[NMAX];        // rsqrt(in_degree + 1)
__device__ int   g_cnt[NMAX];         // in-degree histogram
__device__ int   g_rowptr[NMAX + 1];  // CSR row pointers
__device__ int   g_cursor[NMAX];      // scatter cursors
__device__ int   g_csr[EMAX];         // CSR column (src) indices
__device__ int   g_src[NMAX > EMAX ? NMAX : EMAX]; // extracted int32 src
__device__ int   g_dst[EMAX];         // extracted int32 dst
__device__ int   g_is64;              // 1 if edge_index is int64, else int32

// ---------------- dtype detection -------------------------------------------
__global__ void k_detect(const long long* __restrict__ ei, int E, int N) {
    if (threadIdx.x == 0 && blockIdx.x == 0) {
        int ok = 1;
        int lim = E < 64 ? E : 64;
        for (int i = 0; i < lim; i++) {
            long long v = ei[i];
            if (v < 0 || v >= (long long)N) { ok = 0; break; }
        }
        g_is64 = ok;
    }
}

// ---------------- extract + degree histogram --------------------------------
__global__ void k_zero(int N) {
    int i = blockIdx.x * blockDim.x + threadIdx.x;
    if (i < N) g_cnt[i] = 0;
}

__global__ void k_extract(const void* __restrict__ ei, int E, int N) {
    int i = blockIdx.x * blockDim.x + threadIdx.x;
    if (i >= E) return;
    int s, d;
    if (g_is64) {
        const long long* p = (const long long*)ei;
        s = (int)p[i];
        d = (int)p[i + E];
    } else {
        const int* p = (const int*)ei;
        s = p[i];
        d = p[i + E];
    }
    // hard guards: malformed ids become self-loop-free no-ops
    if (s < 0 || s >= N) s = 0;
    if (d < 0 || d >= N) d = 0;
    g_src[i] = s;
    g_dst[i] = d;
    atomicAdd(&g_cnt[d], 1);
}

// single-block inclusive scan with carry; also emits rowptr, cursor, dinv
__global__ void k_scan(int N) {
    __shared__ int wsum[32];
    __shared__ int s_carry;
    if (threadIdx.x == 0) { s_carry = 0; g_rowptr[0] = 0; }
    __syncthreads();
    const int lane = threadIdx.x & 31;
    const int wid  = threadIdx.x >> 5;
    for (int base = 0; base < N; base += 1024) {
        int i = base + threadIdx.x;
        int v = (i < N) ? g_cnt[i] : 0;
        int x = v;
        #pragma unroll
        for (int o = 1; o < 32; o <<= 1) {
            int y = __shfl_up_sync(0xffffffffu, x, o);
            if (lane >= o) x += y;
        }
        if (lane == 31) wsum[wid] = x;
        __syncthreads();
        if (wid == 0) {
            int w = wsum[lane];
            #pragma unroll
            for (int o = 1; o < 32; o <<= 1) {
                int y = __shfl_up_sync(0xffffffffu, w, o);
                if (lane >= o) w += y;
            }
            wsum[lane] = w;
        }
        __syncthreads();
        int incl = x + (wid ? wsum[wid - 1] : 0) + s_carry;
        if (i < N) {
            g_rowptr[i + 1] = incl;
            g_cursor[i]     = incl - v;                 // == rowptr[i]
            g_dinv[i]       = rsqrtf((float)(v + 1));   // +1 self-loop
        }
        __syncthreads();
        if (threadIdx.x == 1023) s_carry = incl;
        __syncthreads();
    }
}

__global__ void k_scatter(int E) {
    int i = blockIdx.x * blockDim.x + threadIdx.x;
    if (i < E) {
        int d = g_dst[i];
        int p = atomicAdd(&g_cursor[d], 1);
        if (p >= 0 && p < EMAX) g_csr[p] = g_src[i];
    }
}

// ---------------- fp32 register-tiled GEMM: C[M,BN] = A[M,128] @ W[128,BN] --
template <int BN, int TN>
__global__ __launch_bounds__(256) void k_gemm(const float* __restrict__ A,
                                              const float* __restrict__ W,
                                              float* __restrict__ C, int M) {
    constexpr int BM = 64, BK = 32, TM = 4;
    __shared__ float As[BK][BM + 1];
    __shared__ float Ws[BK][BN];
    const int tx = threadIdx.x % (BN / TN);
    const int ty = threadIdx.x / (BN / TN);
    const int m0 = blockIdx.x * BM;

    float acc[TM][TN];
    #pragma unroll
    for (int i = 0; i < TM; i++)
        #pragma unroll
        for (int j = 0; j < TN; j++) acc[i][j] = 0.f;

    for (int k0 = 0; k0 < 128; k0 += BK) {
        int kk = threadIdx.x & 31, mb = threadIdx.x >> 5;
        #pragma unroll
        for (int j = 0; j < 8; j++) {
            int m = mb + j * 8, gm = m0 + m;
            As[kk][m] = (gm < M) ? A[(size_t)gm * 128 + k0 + kk] : 0.f;
        }
        #pragma unroll
        for (int j = 0; j < (BK * BN) / 256; j++) {
            int idx = threadIdx.x + j * 256;
            int k = idx / BN, n = idx % BN;
            Ws[k][n] = W[(k0 + k) * BN + n];
        }
        __syncthreads();
        #pragma unroll
        for (int k = 0; k < BK; k++) {
            float a[TM], b[TN];
            #pragma unroll
            for (int i = 0; i < TM; i++) a[i] = As[k][ty * TM + i];
            #pragma unroll
            for (int j = 0; j < TN; j++) b[j] = Ws[k][tx * TN + j];
            #pragma unroll
            for (int i = 0; i < TM; i++)
                #pragma unroll
                for (int j = 0; j < TN; j++) acc[i][j] = fmaf(a[i], b[j], acc[i][j]);
        }
        __syncthreads();
    }
    #pragma unroll
    for (int i = 0; i < TM; i++) {
        int gm = m0 + ty * TM + i;
        if (gm < M) {
            #pragma unroll
            for (int j = 0; j < TN; j++)
                C[(size_t)gm * BN + tx * TN + j] = acc[i][j];
        }
    }
}

// ---------------- layer-1 aggregation + bias + ReLU (F=128, warp/node) ------
__global__ __launch_bounds__(256) void k_agg1(const float* __restrict__ xw,
                                              const float* __restrict__ bias,
                                              float* __restrict__ out, int N) {
    int node = blockIdx.x * (blockDim.x >> 5) + (threadIdx.x >> 5);
    if (node >= N) return;
    int lane = threadIdx.x & 31;
    float di = g_dinv[node];

    float4 sv = ((const float4*)(xw + (size_t)node * 128))[lane];
    float4 acc = make_float4(sv.x * di, sv.y * di, sv.z * di, sv.w * di);

    int e = g_rowptr[node], end = g_rowptr[node + 1];
    for (; e + 1 < end; e += 2) {
        int s0 = g_csr[e], s1 = g_csr[e + 1];
        float w0 = g_dinv[s0], w1 = g_dinv[s1];
        float4 v0 = ((const float4*)(xw + (size_t)s0 * 128))[lane];
        float4 v1 = ((const float4*)(xw + (size_t)s1 * 128))[lane];
        acc.x += v0.x * w0 + v1.x * w1;
        acc.y += v0.y * w0 + v1.y * w1;
        acc.z += v0.z * w0 + v1.z * w1;
        acc.w += v0.w * w0 + v1.w * w1;
    }
    if (e < end) {
        int s = g_csr[e];
        float w = g_dinv[s];
        float4 v = ((const float4*)(xw + (size_t)s * 128))[lane];
        acc.x += v.x * w; acc.y += v.y * w; acc.z += v.z * w; acc.w += v.w * w;
    }
    float4 bb = ((const float4*)bias)[lane];
    float4 r;
    r.x = fmaxf(fmaf(acc.x, di, bb.x), 0.f);
    r.y = fmaxf(fmaf(acc.y, di, bb.y), 0.f);
    r.z = fmaxf(fmaf(acc.z, di, bb.z), 0.f);
    r.w = fmaxf(fmaf(acc.w, di, bb.w), 0.f);
    ((float4*)(out + (size_t)node * 128))[lane] = r;
}

// ---------------- layer-2 aggregation + bias + log_softmax (F=64) -----------
__global__ __launch_bounds__(256) void k_agg2(const float* __restrict__ xw,
                                              const float* __restrict__ bias,
                                              float* __restrict__ out, int N) {
    int node = blockIdx.x * (blockDim.x >> 5) + (threadIdx.x >> 5);
    if (node >= N) return;
    int lane = threadIdx.x & 31;
    float di = g_dinv[node];

    float2 sv = ((const float2*)(xw + (size_t)node * 64))[lane];
    float2 acc = make_float2(sv.x * di, sv.y * di);

    int e = g_rowptr[node], end = g_rowptr[node + 1];
    for (; e + 1 < end; e += 2) {
        int s0 = g_csr[e], s1 = g_csr[e + 1];
        float w0 = g_dinv[s0], w1 = g_dinv[s1];
        float2 v0 = ((const float2*)(xw + (size_t)s0 * 64))[lane];
        float2 v1 = ((const float2*)(xw + (size_t)s1 * 64))[lane];
        acc.x += v0.x * w0 + v1.x * w1;
        acc.y += v0.y * w0 + v1.y * w1;
    }
    if (e < end) {
        int s = g_csr[e];
        float w = g_dinv[s];
        float2 v = ((const float2*)(xw + (size_t)s * 64))[lane];
        acc.x += v.x * w; acc.y += v.y * w;
    }
    float2 bb = ((const float2*)bias)[lane];
    float vx = fmaf(acc.x, di, bb.x);
    float vy = fmaf(acc.y, di, bb.y);

    // log_softmax over 64 values (2 per lane)
    float m = fmaxf(vx, vy);
    #pragma unroll
    for (int o = 16; o; o >>= 1) m = fmaxf(m, __shfl_xor_sync(0xffffffffu, m, o));
    float s = expf(vx - m) + expf(vy - m);
    #pragma unroll
    for (int o = 16; o; o >>= 1) s += __shfl_xor_sync(0xffffffffu, s, o);
    float lse = m + logf(s);
    ((float2*)(out + (size_t)node * 64))[lane] = make_float2(vx - lse, vy - lse);
}

// ---------------- launcher ---------------------------------------------------
extern "C" void kernel_launch(void* const* d_in, const int* in_sizes, int n_in,
                              void* d_out, int out_size) {
    const float* x   = (const float*)d_in[0];
    const void*  ei  = d_in[1];
    const float* W1  = (const float*)d_in[2];
    const float* b1  = (const float*)d_in[3];
    const float* W2  = (const float*)d_in[4];
    const float* b2  = (const float*)d_in[5];
    float*       out = (float*)d_out;

    const int N = in_sizes[0] / 128;
    const int E = in_sizes[1] / 2;

    float *xw1, *h, *xw2;
    cudaGetSymbolAddress((void**)&xw1, g_xw1);
    cudaGetSymbolAddress((void**)&h,   g_h);
    cudaGetSymbolAddress((void**)&xw2, g_xw2);

    // CSR build (dtype-robust)
    k_detect <<<1, 32>>>((const long long*)ei, E, N);
    k_zero   <<<(N + 255) / 256, 256>>>(N);
    k_extract<<<(E + 255) / 256, 256>>>(ei, E, N);
    k_scan   <<<1, 1024>>>(N);
    k_scatter<<<(E + 255) / 256, 256>>>(E);

    // Layer 1: xw1 = x @ W1 ; h = relu(A_hat @ xw1 + b1)
    k_gemm<128, 8><<<(N + 63) / 64, 256>>>(x, W1, xw1, N);
    k_agg1<<<(N + 7) / 8, 256>>>(xw1, b1, h, N);

    // Layer 2: xw2 = h @ W2 ; out = log_softmax(A_hat @ xw2 + b2)
    k_gemm<64, 4><<<(N + 63) / 64, 256>>>(h, W2, xw2, N);
    k_agg2<<<(N + 7) / 8, 256>>>(xw2, b2, out, N);
}

// round 7
// speedup vs baseline: 1.1902x; 1.1902x over previous
#include <cuda_runtime.h>
#include <math.h>

// ---------------- problem-size scratch (device globals: allocation-free) ----
#define NMAX 100000
#define EMAX 1600000
#define SCAN_TILE 4096                 // 1024 threads * 4 items
#define MAX_SCAN_BLOCKS ((NMAX + SCAN_TILE - 1) / SCAN_TILE)

__device__ float g_xw1[NMAX * 128];   // x @ W1
__device__ float g_h  [NMAX * 128];   // layer-1 output (post agg+bias+relu)
__device__ float g_xw2[NMAX * 64];    // h @ W2
__device__ float g_dinv[NMAX];        // rsqrt(in_degree + 1)
__device__ int   g_cnt[NMAX];         // in-degree histogram
__device__ int   g_rowptr[NMAX + 1];  // CSR row pointers
__device__ int   g_cursor[NMAX];      // scatter cursors
__device__ int   g_csr[EMAX];         // CSR column (src) indices
__device__ int   g_src[EMAX];         // extracted int32 src
__device__ int   g_dst[EMAX];         // extracted int32 dst
__device__ int   g_is64;              // 1 if edge_index is int64, else int32
__device__ int   g_bsum[MAX_SCAN_BLOCKS];  // per-block scan sums
__device__ int   g_boff[MAX_SCAN_BLOCKS];  // exclusive block offsets

// ---------------- dtype detection -------------------------------------------
__global__ void k_detect(const long long* __restrict__ ei, int E, int N) {
    if (threadIdx.x == 0 && blockIdx.x == 0) {
        int ok = 1;
        int lim = E < 64 ? E : 64;
        for (int i = 0; i < lim; i++) {
            long long v = ei[i];
            if (v < 0 || v >= (long long)N) { ok = 0; break; }
        }
        g_is64 = ok;
    }
}

// ---------------- extract + degree histogram --------------------------------
__global__ void k_zero(int N) {
    int i = blockIdx.x * blockDim.x + threadIdx.x;
    if (i < N) g_cnt[i] = 0;
}

__global__ void k_extract(const void* __restrict__ ei, int E, int N) {
    int i = blockIdx.x * blockDim.x + threadIdx.x;
    if (i >= E) return;
    int s, d;
    if (g_is64) {
        const long long* p = (const long long*)ei;
        s = (int)p[i];
        d = (int)p[i + E];
    } else {
        const int* p = (const int*)ei;
        s = p[i];
        d = p[i + E];
    }
    if (s < 0 || s >= N) s = 0;
    if (d < 0 || d >= N) d = 0;
    g_src[i] = s;
    g_dst[i] = d;
    atomicAdd(&g_cnt[d], 1);
}

// ---------------- 3-phase multi-block scan -----------------------------------
// Phase A: per-block inclusive scan of g_cnt into g_rowptr[i+1] (block-local),
//          per-block totals into g_bsum.
__global__ __launch_bounds__(1024) void k_scanA(int N) {
    __shared__ int wsum[32];
    const int lane = threadIdx.x & 31;
    const int wid  = threadIdx.x >> 5;
    const int base = blockIdx.x * SCAN_TILE + threadIdx.x * 4;

    int v0 = 0, v1 = 0, v2 = 0, v3 = 0;
    if (base + 3 < N) {
        v0 = g_cnt[base]; v1 = g_cnt[base + 1];
        v2 = g_cnt[base + 2]; v3 = g_cnt[base + 3];
    } else {
        if (base     < N) v0 = g_cnt[base];
        if (base + 1 < N) v1 = g_cnt[base + 1];
        if (base + 2 < N) v2 = g_cnt[base + 2];
        if (base + 3 < N) v3 = g_cnt[base + 3];
    }
    // thread-local inclusive
    int p0 = v0, p1 = p0 + v1, p2 = p1 + v2, p3 = p2 + v3;
    // warp inclusive scan of thread sums
    int x = p3;
    #pragma unroll
    for (int o = 1; o < 32; o <<= 1) {
        int y = __shfl_up_sync(0xffffffffu, x, o);
        if (lane >= o) x += y;
    }
    if (lane == 31) wsum[wid] = x;
    __syncthreads();
    if (wid == 0) {
        int w = (lane < 32) ? wsum[lane] : 0;
        #pragma unroll
        for (int o = 1; o < 32; o <<= 1) {
            int y = __shfl_up_sync(0xffffffffu, w, o);
            if (lane >= o) w += y;
        }
        wsum[lane] = w;
    }
    __syncthreads();
    int texcl = (x - p3) + (wid ? wsum[wid - 1] : 0);   // exclusive offset for this thread
    if (base     < N) g_rowptr[base + 1] = texcl + p0;
    if (base + 1 < N) g_rowptr[base + 2] = texcl + p1;
    if (base + 2 < N) g_rowptr[base + 3] = texcl + p2;
    if (base + 3 < N) g_rowptr[base + 4] = texcl + p3;
    if (threadIdx.x == 1023) g_bsum[blockIdx.x] = wsum[31];
}

// Phase B: one warp exclusive-scans the block sums.
__global__ void k_scanB(int nblocks) {
    int lane = threadIdx.x;
    int v = (lane < nblocks) ? g_bsum[lane] : 0;
    int x = v;
    #pragma unroll
    for (int o = 1; o < 32; o <<= 1) {
        int y = __shfl_up_sync(0xffffffffu, x, o);
        if (lane >= o) x += y;
    }
    if (lane < nblocks) g_boff[lane] = x - v;   // exclusive
}

// Phase C: add block offsets; emit final rowptr, cursor, dinv.
__global__ __launch_bounds__(1024) void k_scanC(int N) {
    int i = blockIdx.x * blockDim.x + threadIdx.x;
    if (i == 0) g_rowptr[0] = 0;
    if (i < N) {
        int incl = g_rowptr[i + 1] + g_boff[i / SCAN_TILE];
        int v = g_cnt[i];
        g_rowptr[i + 1] = incl;
        g_cursor[i]     = incl - v;
        g_dinv[i]       = rsqrtf((float)(v + 1));
    }
}

__global__ void k_scatter(int E) {
    int i = blockIdx.x * blockDim.x + threadIdx.x;
    if (i < E) {
        int d = g_dst[i];
        int p = atomicAdd(&g_cursor[d], 1);
        if (p >= 0 && p < EMAX) g_csr[p] = g_src[i];
    }
}

// ---------------- fp32 register-tiled GEMM: C[M,BN] = A[M,128] @ W[128,BN] --
template <int BN, int TN>
__global__ __launch_bounds__(256) void k_gemm(const float* __restrict__ A,
                                              const float* __restrict__ W,
                                              float* __restrict__ C, int M) {
    constexpr int BM = 64, BK = 32, TM = 4;
    __shared__ float As[BK][BM + 1];
    __shared__ float Ws[BK][BN];
    const int tx = threadIdx.x % (BN / TN);
    const int ty = threadIdx.x / (BN / TN);
    const int m0 = blockIdx.x * BM;

    float acc[TM][TN];
    #pragma unroll
    for (int i = 0; i < TM; i++)
        #pragma unroll
        for (int j = 0; j < TN; j++) acc[i][j] = 0.f;

    for (int k0 = 0; k0 < 128; k0 += BK) {
        int kk = threadIdx.x & 31, mb = threadIdx.x >> 5;
        #pragma unroll
        for (int j = 0; j < 8; j++) {
            int m = mb + j * 8, gm = m0 + m;
            As[kk][m] = (gm < M) ? A[(size_t)gm * 128 + k0 + kk] : 0.f;
        }
        #pragma unroll
        for (int j = 0; j < (BK * BN) / 256; j++) {
            int idx = threadIdx.x + j * 256;
            int k = idx / BN, n = idx % BN;
            Ws[k][n] = W[(k0 + k) * BN + n];
        }
        __syncthreads();
        #pragma unroll
        for (int k = 0; k < BK; k++) {
            float a[TM], b[TN];
            #pragma unroll
            for (int i = 0; i < TM; i++) a[i] = As[k][ty * TM + i];
            #pragma unroll
            for (int j = 0; j < TN; j++) b[j] = Ws[k][tx * TN + j];
            #pragma unroll
            for (int i = 0; i < TM; i++)
                #pragma unroll
                for (int j = 0; j < TN; j++) acc[i][j] = fmaf(a[i], b[j], acc[i][j]);
        }
        __syncthreads();
    }
    #pragma unroll
    for (int i = 0; i < TM; i++) {
        int gm = m0 + ty * TM + i;
        if (gm < M) {
            #pragma unroll
            for (int j = 0; j < TN; j++)
                C[(size_t)gm * BN + tx * TN + j] = acc[i][j];
        }
    }
}

// ---------------- layer-1 aggregation + bias + ReLU (F=128, warp/node) ------
__global__ __launch_bounds__(256) void k_agg1(const float* __restrict__ xw,
                                              const float* __restrict__ bias,
                                              float* __restrict__ out, int N) {
    int node = blockIdx.x * (blockDim.x >> 5) + (threadIdx.x >> 5);
    if (node >= N) return;
    int lane = threadIdx.x & 31;
    float di = g_dinv[node];

    float4 sv = ((const float4*)(xw + (size_t)node * 128))[lane];
    float4 acc = make_float4(sv.x * di, sv.y * di, sv.z * di, sv.w * di);

    int e = g_rowptr[node], end = g_rowptr[node + 1];
    for (; e + 1 < end; e += 2) {
        int s0 = g_csr[e], s1 = g_csr[e + 1];
        float w0 = g_dinv[s0], w1 = g_dinv[s1];
        float4 v0 = ((const float4*)(xw + (size_t)s0 * 128))[lane];
        float4 v1 = ((const float4*)(xw + (size_t)s1 * 128))[lane];
        acc.x += v0.x * w0 + v1.x * w1;
        acc.y += v0.y * w0 + v1.y * w1;
        acc.z += v0.z * w0 + v1.z * w1;
        acc.w += v0.w * w0 + v1.w * w1;
    }
    if (e < end) {
        int s = g_csr[e];
        float w = g_dinv[s];
        float4 v = ((const float4*)(xw + (size_t)s * 128))[lane];
        acc.x += v.x * w; acc.y += v.y * w; acc.z += v.z * w; acc.w += v.w * w;
    }
    float4 bb = ((const float4*)bias)[lane];
    float4 r;
    r.x = fmaxf(fmaf(acc.x, di, bb.x), 0.f);
    r.y = fmaxf(fmaf(acc.y, di, bb.y), 0.f);
    r.z = fmaxf(fmaf(acc.z, di, bb.z), 0.f);
    r.w = fmaxf(fmaf(acc.w, di, bb.w), 0.f);
    ((float4*)(out + (size_t)node * 128))[lane] = r;
}

// ---------------- layer-2 aggregation + bias + log_softmax (F=64) -----------
__global__ __launch_bounds__(256) void k_agg2(const float* __restrict__ xw,
                                              const float* __restrict__ bias,
                                              float* __restrict__ out, int N) {
    int node = blockIdx.x * (blockDim.x >> 5) + (threadIdx.x >> 5);
    if (node >= N) return;
    int lane = threadIdx.x & 31;
    float di = g_dinv[node];

    float2 sv = ((const float2*)(xw + (size_t)node * 64))[lane];
    float2 acc = make_float2(sv.x * di, sv.y * di);

    int e = g_rowptr[node], end = g_rowptr[node + 1];
    for (; e + 1 < end; e += 2) {
        int s0 = g_csr[e], s1 = g_csr[e + 1];
        float w0 = g_dinv[s0], w1 = g_dinv[s1];
        float2 v0 = ((const float2*)(xw + (size_t)s0 * 64))[lane];
        float2 v1 = ((const float2*)(xw + (size_t)s1 * 64))[lane];
        acc.x += v0.x * w0 + v1.x * w1;
        acc.y += v0.y * w0 + v1.y * w1;
    }
    if (e < end) {
        int s = g_csr[e];
        float w = g_dinv[s];
        float2 v = ((const float2*)(xw + (size_t)s * 64))[lane];
        acc.x += v.x * w; acc.y += v.y * w;
    }
    float2 bb = ((const float2*)bias)[lane];
    float vx = fmaf(acc.x, di, bb.x);
    float vy = fmaf(acc.y, di, bb.y);

    float m = fmaxf(vx, vy);
    #pragma unroll
    for (int o = 16; o; o >>= 1) m = fmaxf(m, __shfl_xor_sync(0xffffffffu, m, o));
    float s = expf(vx - m) + expf(vy - m);
    #pragma unroll
    for (int o = 16; o; o >>= 1) s += __shfl_xor_sync(0xffffffffu, s, o);
    float lse = m + logf(s);
    ((float2*)(out + (size_t)node * 64))[lane] = make_float2(vx - lse, vy - lse);
}

// ---------------- launcher ---------------------------------------------------
extern "C" void kernel_launch(void* const* d_in, const int* in_sizes, int n_in,
                              void* d_out, int out_size) {
    const float* x   = (const float*)d_in[0];
    const void*  ei  = d_in[1];
    const float* W1  = (const float*)d_in[2];
    const float* b1  = (const float*)d_in[3];
    const float* W2  = (const float*)d_in[4];
    const float* b2  = (const float*)d_in[5];
    float*       out = (float*)d_out;

    const int N = in_sizes[0] / 128;
    const int E = in_sizes[1] / 2;
    const int nScanBlocks = (N + SCAN_TILE - 1) / SCAN_TILE;

    float *xw1, *h, *xw2;
    cudaGetSymbolAddress((void**)&xw1, g_xw1);
    cudaGetSymbolAddress((void**)&h,   g_h);
    cudaGetSymbolAddress((void**)&xw2, g_xw2);

    // CSR build (dtype-robust, fully parallel scan)
    k_detect <<<1, 32>>>((const long long*)ei, E, N);
    k_zero   <<<(N + 255) / 256, 256>>>(N);
    k_extract<<<(E + 255) / 256, 256>>>(ei, E, N);
    k_scanA  <<<nScanBlocks, 1024>>>(N);
    k_scanB  <<<1, 32>>>(nScanBlocks);
    k_scanC  <<<(N + 1023) / 1024, 1024>>>(N);
    k_scatter<<<(E + 255) / 256, 256>>>(E);

    // Layer 1: xw1 = x @ W1 ; h = relu(A_hat @ xw1 + b1)
    k_gemm<128, 8><<<(N + 63) / 64, 256>>>(x, W1, xw1, N);
    k_agg1<<<(N + 7) / 8, 256>>>(xw1, b1, h, N);

    // Layer 2: xw2 = h @ W2 ; out = log_softmax(A_hat @ xw2 + b2)
    k_gemm<64, 4><<<(N + 63) / 64, 256>>>(h, W2, xw2, N);
    k_agg2<<<(N + 7) / 8, 256>>>(xw2, b2, out, N);
}

// round 8
// speedup vs baseline: 1.9933x; 1.6747x over previous
#include <cuda_runtime.h>
#include <math.h>
#include <stdint.h>

// ---------------- problem-size scratch (device globals: allocation-free) ----
#define NMAX 100000
#define EMAX 1600000
#define SCAN_TILE 4096
#define MAX_SCAN_BLOCKS ((NMAX + SCAN_TILE - 1) / SCAN_TILE)

__device__ float g_xw1[NMAX * 128];   // x @ W1
__device__ float g_h  [NMAX * 128];   // layer-1 output (post agg+bias+relu)
__device__ float g_xw2[NMAX * 64];    // h @ W2
__device__ float g_dinv[NMAX];        // rsqrt(in_degree + 1)
__device__ int   g_cnt[NMAX];
__device__ int   g_rowptr[NMAX + 1];
__device__ int   g_cursor[NMAX];
__device__ int   g_csr[EMAX];
__device__ int   g_src[EMAX];
__device__ int   g_dst[EMAX];
__device__ int   g_is64;
__device__ int   g_bsum[MAX_SCAN_BLOCKS];
__device__ int   g_boff[MAX_SCAN_BLOCKS];
__device__ float g_bf1[16 * 16 * 64]; // W1 mma fragments [ks][nf][lane][2]
__device__ float g_bf2[16 * 8 * 64];  // W2 mma fragments

// ---------------- mma helpers ------------------------------------------------
__device__ __forceinline__ float cvt_tf32(float x) {
    uint32_t r; asm("cvt.rna.tf32.f32 %0, %1;" : "=r"(r) : "f"(x));
    return __uint_as_float(r);
}
__device__ __forceinline__ uint32_t smem_u32(const void* p) {
    return (uint32_t)__cvta_generic_to_shared(p);
}
__device__ __forceinline__ void ldsm4(uint32_t& r0, uint32_t& r1, uint32_t& r2,
                                      uint32_t& r3, uint32_t a) {
    asm volatile("ldmatrix.sync.aligned.m8n8.x4.shared.b16 {%0,%1,%2,%3}, [%4];"
                 : "=r"(r0), "=r"(r1), "=r"(r2), "=r"(r3) : "r"(a));
}
__device__ __forceinline__ void mma_tf32(float c[4], const uint32_t a[4],
                                         uint32_t b0, uint32_t b1) {
    asm volatile("mma.sync.aligned.m16n8k8.row.col.f32.tf32.tf32.f32 "
                 "{%0,%1,%2,%3}, {%4,%5,%6,%7}, {%8,%9}, {%0,%1,%2,%3};"
                 : "+f"(c[0]), "+f"(c[1]), "+f"(c[2]), "+f"(c[3])
                 : "r"(a[0]), "r"(a[1]), "r"(a[2]), "r"(a[3]), "r"(b0), "r"(b1));
}

// ---------------- W fragment prep (tf32, mma register layout) ----------------
__global__ void k_bfrag(const float* __restrict__ W1, const float* __restrict__ W2) {
    int t = blockIdx.x * blockDim.x + threadIdx.x;
    if (t < 16 * 16 * 64) {
        int j    = t & 1;
        int lane = (t >> 1) & 31;
        int nf   = (t >> 6) & 15;
        int ks   = t >> 10;
        int k = ks * 8 + (lane & 3) + j * 4;
        int n = nf * 8 + (lane >> 2);
        g_bf1[t] = cvt_tf32(W1[k * 128 + n]);
    } else {
        int u = t - 16 * 16 * 64;
        if (u < 16 * 8 * 64) {
            int j    = u & 1;
            int lane = (u >> 1) & 31;
            int nf   = (u >> 6) & 7;
            int ks   = u >> 9;
            int k = ks * 8 + (lane & 3) + j * 4;
            int n = nf * 8 + (lane >> 2);
            g_bf2[u] = cvt_tf32(W2[k * 64 + n]);
        }
    }
}

// ---------------- tensor-core GEMM: C[M,BN] = A[M,128] @ W[128,BN] ----------
// 4 m-warps x 2 n-warps, block tile 128 x BN, K=128 staged in 2 chunks of 64.
template <int BN>
__global__ __launch_bounds__(256, 2) void k_gemm_tc(const float* __restrict__ A,
                                                    const float* __restrict__ BF,
                                                    float* __restrict__ C, int M) {
    constexpr int NFTOT = BN / 8;     // total n-frags
    constexpr int NF    = NFTOT / 2;  // per-warp n-frags
    constexpr int LDA   = 68;         // smem row stride in floats (64 + 4 pad)
    __shared__ float As[128 * LDA];

    const int tid  = threadIdx.x;
    const int lane = tid & 31;
    const int wid  = tid >> 5;
    const int wm   = wid & 3;
    const int wn   = wid >> 2;
    const int m0   = blockIdx.x * 128;

    float c[2][NF][4];
    #pragma unroll
    for (int mf = 0; mf < 2; mf++)
        #pragma unroll
        for (int nf = 0; nf < NF; nf++)
            #pragma unroll
            for (int i = 0; i < 4; i++) c[mf][nf][i] = 0.f;

    // ldmatrix base: row = wm*32 + (lane&15), col floats = (lane>>4)*4
    const uint32_t a_base =
        smem_u32(As) + (((wm * 32 + (lane & 15)) * LDA + (lane >> 4) * 4) << 2);

    #pragma unroll
    for (int half = 0; half < 2; half++) {
        // stage 128 rows x 64 cols (tf32-rounded), 16 float4-lanes per row
        #pragma unroll
        for (int it = 0; it < 8; it++) {
            int r  = (tid >> 4) + it * 16;
            int q  = tid & 15;
            int gm = m0 + r;
            float4 v = make_float4(0.f, 0.f, 0.f, 0.f);
            if (gm < M)
                v = *(const float4*)(A + (size_t)gm * 128 + half * 64 + q * 4);
            v.x = cvt_tf32(v.x); v.y = cvt_tf32(v.y);
            v.z = cvt_tf32(v.z); v.w = cvt_tf32(v.w);
            *(float4*)(As + r * LDA + q * 4) = v;
        }
        __syncthreads();

        #pragma unroll
        for (int ks = 0; ks < 8; ks++) {
            uint32_t a[2][4];
            #pragma unroll
            for (int mf = 0; mf < 2; mf++)
                ldsm4(a[mf][0], a[mf][1], a[mf][2], a[mf][3],
                      a_base + mf * (16 * LDA * 4) + ks * 32);
            int ksg = half * 8 + ks;
            #pragma unroll
            for (int nf = 0; nf < NF; nf++) {
                float2 b = __ldg((const float2*)BF +
                                 (size_t)(ksg * NFTOT + wn * NF + nf) * 32 + lane);
                uint32_t b0 = __float_as_uint(b.x), b1 = __float_as_uint(b.y);
                mma_tf32(c[0][nf], a[0], b0, b1);
                mma_tf32(c[1][nf], a[1], b0, b1);
            }
        }
        __syncthreads();
    }

    // epilogue
    #pragma unroll
    for (int mf = 0; mf < 2; mf++) {
        int r0 = m0 + wm * 32 + mf * 16 + (lane >> 2);
        int cb = wn * (BN / 2) + (lane & 3) * 2;
        #pragma unroll
        for (int nf = 0; nf < NF; nf++) {
            int n = cb + nf * 8;
            if (r0 < M)
                *(float2*)(C + (size_t)r0 * BN + n) = make_float2(c[mf][nf][0], c[mf][nf][1]);
            if (r0 + 8 < M)
                *(float2*)(C + (size_t)(r0 + 8) * BN + n) = make_float2(c[mf][nf][2], c[mf][nf][3]);
        }
    }
}

// ---------------- dtype detection -------------------------------------------
__global__ void k_detect(const long long* __restrict__ ei, int E, int N) {
    if (threadIdx.x == 0 && blockIdx.x == 0) {
        int ok = 1;
        int lim = E < 64 ? E : 64;
        for (int i = 0; i < lim; i++) {
            long long v = ei[i];
            if (v < 0 || v >= (long long)N) { ok = 0; break; }
        }
        g_is64 = ok;
    }
}

// ---------------- extract + degree histogram --------------------------------
__global__ void k_zero(int N) {
    int i = blockIdx.x * blockDim.x + threadIdx.x;
    if (i < N) g_cnt[i] = 0;
}

__global__ void k_extract(const void* __restrict__ ei, int E, int N) {
    int i = blockIdx.x * blockDim.x + threadIdx.x;
    if (i >= E) return;
    int s, d;
    if (g_is64) {
        const long long* p = (const long long*)ei;
        s = (int)p[i];
        d = (int)p[i + E];
    } else {
        const int* p = (const int*)ei;
        s = p[i];
        d = p[i + E];
    }
    if (s < 0 || s >= N) s = 0;
    if (d < 0 || d >= N) d = 0;
    g_src[i] = s;
    g_dst[i] = d;
    atomicAdd(&g_cnt[d], 1);
}

// ---------------- 3-phase multi-block scan -----------------------------------
__global__ __launch_bounds__(1024) void k_scanA(int N) {
    __shared__ int wsum[32];
    const int lane = threadIdx.x & 31;
    const int wid  = threadIdx.x >> 5;
    const int base = blockIdx.x * SCAN_TILE + threadIdx.x * 4;

    int v0 = 0, v1 = 0, v2 = 0, v3 = 0;
    if (base + 3 < N) {
        v0 = g_cnt[base]; v1 = g_cnt[base + 1];
        v2 = g_cnt[base + 2]; v3 = g_cnt[base + 3];
    } else {
        if (base     < N) v0 = g_cnt[base];
        if (base + 1 < N) v1 = g_cnt[base + 1];
        if (base + 2 < N) v2 = g_cnt[base + 2];
        if (base + 3 < N) v3 = g_cnt[base + 3];
    }
    int p0 = v0, p1 = p0 + v1, p2 = p1 + v2, p3 = p2 + v3;
    int x = p3;
    #pragma unroll
    for (int o = 1; o < 32; o <<= 1) {
        int y = __shfl_up_sync(0xffffffffu, x, o);
        if (lane >= o) x += y;
    }
    if (lane == 31) wsum[wid] = x;
    __syncthreads();
    if (wid == 0) {
        int w = wsum[lane];
        #pragma unroll
        for (int o = 1; o < 32; o <<= 1) {
            int y = __shfl_up_sync(0xffffffffu, w, o);
            if (lane >= o) w += y;
        }
        wsum[lane] = w;
    }
    __syncthreads();
    int texcl = (x - p3) + (wid ? wsum[wid - 1] : 0);
    if (base     < N) g_rowptr[base + 1] = texcl + p0;
    if (base + 1 < N) g_rowptr[base + 2] = texcl + p1;
    if (base + 2 < N) g_rowptr[base + 3] = texcl + p2;
    if (base + 3 < N) g_rowptr[base + 4] = texcl + p3;
    if (threadIdx.x == 1023) g_bsum[blockIdx.x] = wsum[31];
}

__global__ void k_scanB(int nblocks) {
    int lane = threadIdx.x;
    int v = (lane < nblocks) ? g_bsum[lane] : 0;
    int x = v;
    #pragma unroll
    for (int o = 1; o < 32; o <<= 1) {
        int y = __shfl_up_sync(0xffffffffu, x, o);
        if (lane >= o) x += y;
    }
    if (lane < nblocks) g_boff[lane] = x - v;
}

__global__ __launch_bounds__(1024) void k_scanC(int N) {
    int i = blockIdx.x * blockDim.x + threadIdx.x;
    if (i == 0) g_rowptr[0] = 0;
    if (i < N) {
        int incl = g_rowptr[i + 1] + g_boff[i / SCAN_TILE];
        int v = g_cnt[i];
        g_rowptr[i + 1] = incl;
        g_cursor[i]     = incl - v;
        g_dinv[i]       = rsqrtf((float)(v + 1));
    }
}

__global__ void k_scatter(int E) {
    int i = blockIdx.x * blockDim.x + threadIdx.x;
    if (i < E) {
        int d = g_dst[i];
        int p = atomicAdd(&g_cursor[d], 1);
        if (p >= 0 && p < EMAX) g_csr[p] = g_src[i];
    }
}

// ---------------- layer-1 aggregation + bias + ReLU (F=128, warp/node) ------
__global__ __launch_bounds__(256) void k_agg1(const float* __restrict__ xw,
                                              const float* __restrict__ bias,
                                              float* __restrict__ out, int N) {
    int node = blockIdx.x * (blockDim.x >> 5) + (threadIdx.x >> 5);
    if (node >= N) return;
    int lane = threadIdx.x & 31;
    float di = g_dinv[node];

    float4 sv = ((const float4*)(xw + (size_t)node * 128))[lane];
    float4 acc = make_float4(sv.x * di, sv.y * di, sv.z * di, sv.w * di);

    int e = g_rowptr[node], end = g_rowptr[node + 1];
    for (; e + 1 < end; e += 2) {
        int s0 = g_csr[e], s1 = g_csr[e + 1];
        float w0 = g_dinv[s0], w1 = g_dinv[s1];
        float4 v0 = ((const float4*)(xw + (size_t)s0 * 128))[lane];
        float4 v1 = ((const float4*)(xw + (size_t)s1 * 128))[lane];
        acc.x += v0.x * w0 + v1.x * w1;
        acc.y += v0.y * w0 + v1.y * w1;
        acc.z += v0.z * w0 + v1.z * w1;
        acc.w += v0.w * w0 + v1.w * w1;
    }
    if (e < end) {
        int s = g_csr[e];
        float w = g_dinv[s];
        float4 v = ((const float4*)(xw + (size_t)s * 128))[lane];
        acc.x += v.x * w; acc.y += v.y * w; acc.z += v.z * w; acc.w += v.w * w;
    }
    float4 bb = ((const float4*)bias)[lane];
    float4 r;
    r.x = fmaxf(fmaf(acc.x, di, bb.x), 0.f);
    r.y = fmaxf(fmaf(acc.y, di, bb.y), 0.f);
    r.z = fmaxf(fmaf(acc.z, di, bb.z), 0.f);
    r.w = fmaxf(fmaf(acc.w, di, bb.w), 0.f);
    ((float4*)(out + (size_t)node * 128))[lane] = r;
}

// ---------------- layer-2 aggregation + bias + log_softmax (F=64) -----------
__global__ __launch_bounds__(256) void k_agg2(const float* __restrict__ xw,
                                              const float* __restrict__ bias,
                                              float* __restrict__ out, int N) {
    int node = blockIdx.x * (blockDim.x >> 5) + (threadIdx.x >> 5);
    if (node >= N) return;
    int lane = threadIdx.x & 31;
    float di = g_dinv[node];

    float2 sv = ((const float2*)(xw + (size_t)node * 64))[lane];
    float2 acc = make_float2(sv.x * di, sv.y * di);

    int e = g_rowptr[node], end = g_rowptr[node + 1];
    for (; e + 1 < end; e += 2) {
        int s0 = g_csr[e], s1 = g_csr[e + 1];
        float w0 = g_dinv[s0], w1 = g_dinv[s1];
        float2 v0 = ((const float2*)(xw + (size_t)s0 * 64))[lane];
        float2 v1 = ((const float2*)(xw + (size_t)s1 * 64))[lane];
        acc.x += v0.x * w0 + v1.x * w1;
        acc.y += v0.y * w0 + v1.y * w1;
    }
    if (e < end) {
        int s = g_csr[e];
        float w = g_dinv[s];
        float2 v = ((const float2*)(xw + (size_t)s * 64))[lane];
        acc.x += v.x * w; acc.y += v.y * w;
    }
    float2 bb = ((const float2*)bias)[lane];
    float vx = fmaf(acc.x, di, bb.x);
    float vy = fmaf(acc.y, di, bb.y);

    float m = fmaxf(vx, vy);
    #pragma unroll
    for (int o = 16; o; o >>= 1) m = fmaxf(m, __shfl_xor_sync(0xffffffffu, m, o));
    float s = expf(vx - m) + expf(vy - m);
    #pragma unroll
    for (int o = 16; o; o >>= 1) s += __shfl_xor_sync(0xffffffffu, s, o);
    float lse = m + logf(s);
    ((float2*)(out + (size_t)node * 64))[lane] = make_float2(vx - lse, vy - lse);
}

// ---------------- launcher ---------------------------------------------------
extern "C" void kernel_launch(void* const* d_in, const int* in_sizes, int n_in,
                              void* d_out, int out_size) {
    const float* x   = (const float*)d_in[0];
    const void*  ei  = d_in[1];
    const float* W1  = (const float*)d_in[2];
    const float* b1  = (const float*)d_in[3];
    const float* W2  = (const float*)d_in[4];
    const float* b2  = (const float*)d_in[5];
    float*       out = (float*)d_out;

    const int N = in_sizes[0] / 128;
    const int E = in_sizes[1] / 2;
    const int nScanBlocks = (N + SCAN_TILE - 1) / SCAN_TILE;

    float *xw1, *h, *xw2, *bf1, *bf2;
    cudaGetSymbolAddress((void**)&xw1, g_xw1);
    cudaGetSymbolAddress((void**)&h,   g_h);
    cudaGetSymbolAddress((void**)&xw2, g_xw2);
    cudaGetSymbolAddress((void**)&bf1, g_bf1);
    cudaGetSymbolAddress((void**)&bf2, g_bf2);

    // W fragment prep (independent of everything else)
    k_bfrag<<<(16 * 16 * 64 + 16 * 8 * 64 + 255) / 256, 256>>>(W1, W2);

    // CSR build (dtype-robust, fully parallel scan)
    k_detect <<<1, 32>>>((const long long*)ei, E, N);
    k_zero   <<<(N + 255) / 256, 256>>>(N);
    k_extract<<<(E + 255) / 256, 256>>>(ei, E, N);
    k_scanA  <<<nScanBlocks, 1024>>>(N);
    k_scanB  <<<1, 32>>>(nScanBlocks);
    k_scanC  <<<(N + 1023) / 1024, 1024>>>(N);
    k_scatter<<<(E + 255) / 256, 256>>>(E);

    const int gBlocks = (N + 127) / 128;

    // Layer 1: xw1 = x @ W1 (tf32 TC) ; h = relu(A_hat @ xw1 + b1)
    k_gemm_tc<128><<<gBlocks, 256>>>(x, bf1, xw1, N);
    k_agg1<<<(N + 7) / 8, 256>>>(xw1, b1, h, N);

    // Layer 2: xw2 = h @ W2 (tf32 TC) ; out = log_softmax(A_hat @ xw2 + b2)
    k_gemm_tc<64><<<gBlocks, 256>>>(h, bf2, xw2, N);
    k_agg2<<<(N + 7) / 8, 256>>>(xw2, b2, out, N);
}

// round 10
// speedup vs baseline: 2.4218x; 1.2150x over previous
#include <cuda_runtime.h>
#include <cuda_fp16.h>
#include <math.h>
#include <stdint.h>

// ---------------- problem-size scratch (device globals: allocation-free) ----
#define NMAX 100000
#define EMAX 1600000
#define SCAN_TILE 4096
#define MAX_SCAN_BLOCKS ((NMAX + SCAN_TILE - 1) / SCAN_TILE)

__device__ __half g_xw1h[NMAX * 128]; // (x @ W1) * dinv[row], fp16
__device__ float  g_h   [NMAX * 128]; // layer-1 output (post agg+bias+relu)
__device__ __half g_xw2h[NMAX * 64];  // (h @ W2) * dinv[row], fp16
__device__ float  g_dinv[NMAX];       // rsqrt(in_degree + 1)
__device__ int    g_cnt[NMAX];
__device__ int    g_rowptr[NMAX + 1];
__device__ int    g_cursor[NMAX];
__device__ int    g_csr[EMAX];
__device__ int    g_is64;
__device__ int    g_bsum[MAX_SCAN_BLOCKS];
__device__ int    g_boff[MAX_SCAN_BLOCKS];
__device__ float  g_bf1[16 * 16 * 64]; // W1 mma fragments
__device__ float  g_bf2[16 * 8 * 64];  // W2 mma fragments

// ---------------- mma helpers ------------------------------------------------
__device__ __forceinline__ float cvt_tf32(float x) {
    uint32_t r; asm("cvt.rna.tf32.f32 %0, %1;" : "=r"(r) : "f"(x));
    return __uint_as_float(r);
}
__device__ __forceinline__ uint32_t smem_u32(const void* p) {
    return (uint32_t)__cvta_generic_to_shared(p);
}
__device__ __forceinline__ void ldsm4(uint32_t& r0, uint32_t& r1, uint32_t& r2,
                                      uint32_t& r3, uint32_t a) {
    asm volatile("ldmatrix.sync.aligned.m8n8.x4.shared.b16 {%0,%1,%2,%3}, [%4];"
                 : "=r"(r0), "=r"(r1), "=r"(r2), "=r"(r3) : "r"(a));
}
__device__ __forceinline__ void mma_tf32(float c[4], const uint32_t a[4],
                                         uint32_t b0, uint32_t b1) {
    asm volatile("mma.sync.aligned.m16n8k8.row.col.f32.tf32.tf32.f32 "
                 "{%0,%1,%2,%3}, {%4,%5,%6,%7}, {%8,%9}, {%0,%1,%2,%3};"
                 : "+f"(c[0]), "+f"(c[1]), "+f"(c[2]), "+f"(c[3])
                 : "r"(a[0]), "r"(a[1]), "r"(a[2]), "r"(a[3]), "r"(b0), "r"(b1));
}

// ---------------- W fragment prep (tf32, mma register layout) ----------------
__global__ void k_bfrag(const float* __restrict__ W1, const float* __restrict__ W2) {
    int t = blockIdx.x * blockDim.x + threadIdx.x;
    if (t < 16 * 16 * 64) {
        int j    = t & 1;
        int lane = (t >> 1) & 31;
        int nf   = (t >> 6) & 15;
        int ks   = t >> 10;
        int k = ks * 8 + (lane & 3) + j * 4;
        int n = nf * 8 + (lane >> 2);
        g_bf1[t] = cvt_tf32(W1[k * 128 + n]);
    } else {
        int u = t - 16 * 16 * 64;
        if (u < 16 * 8 * 64) {
            int j    = u & 1;
            int lane = (u >> 1) & 31;
            int nf   = (u >> 6) & 7;
            int ks   = u >> 9;
            int k = ks * 8 + (lane & 3) + j * 4;
            int n = nf * 8 + (lane >> 2);
            g_bf2[u] = cvt_tf32(W2[k * 64 + n]);
        }
    }
}

// ---------------- tensor-core GEMM: Ch[M,BN] = (A[M,128] @ W) * dinv, fp16 --
template <int BN>
__global__ __launch_bounds__(256, 2) void k_gemm_tc(const float* __restrict__ A,
                                                    const float* __restrict__ BF,
                                                    __half* __restrict__ C,
                                                    const float* __restrict__ dinv,
                                                    int M) {
    constexpr int NFTOT = BN / 8;
    constexpr int NF    = NFTOT / 2;
    constexpr int LDA   = 68;
    __shared__ float As[128 * LDA];

    const int tid  = threadIdx.x;
    const int lane = tid & 31;
    const int wid  = tid >> 5;
    const int wm   = wid & 3;
    const int wn   = wid >> 2;
    const int m0   = blockIdx.x * 128;

    float c[2][NF][4];
    #pragma unroll
    for (int mf = 0; mf < 2; mf++)
        #pragma unroll
        for (int nf = 0; nf < NF; nf++)
            #pragma unroll
            for (int i = 0; i < 4; i++) c[mf][nf][i] = 0.f;

    const uint32_t a_base =
        smem_u32(As) + (((wm * 32 + (lane & 15)) * LDA + (lane >> 4) * 4) << 2);

    #pragma unroll
    for (int half_ = 0; half_ < 2; half_++) {
        #pragma unroll
        for (int it = 0; it < 8; it++) {
            int r  = (tid >> 4) + it * 16;
            int q  = tid & 15;
            int gm = m0 + r;
            float4 v = make_float4(0.f, 0.f, 0.f, 0.f);
            if (gm < M)
                v = *(const float4*)(A + (size_t)gm * 128 + half_ * 64 + q * 4);
            v.x = cvt_tf32(v.x); v.y = cvt_tf32(v.y);
            v.z = cvt_tf32(v.z); v.w = cvt_tf32(v.w);
            *(float4*)(As + r * LDA + q * 4) = v;
        }
        __syncthreads();

        #pragma unroll
        for (int ks = 0; ks < 8; ks++) {
            uint32_t a[2][4];
            #pragma unroll
            for (int mf = 0; mf < 2; mf++)
                ldsm4(a[mf][0], a[mf][1], a[mf][2], a[mf][3],
                      a_base + mf * (16 * LDA * 4) + ks * 32);
            int ksg = half_ * 8 + ks;
            #pragma unroll
            for (int nf = 0; nf < NF; nf++) {
                float2 b = __ldg((const float2*)BF +
                                 (size_t)(ksg * NFTOT + wn * NF + nf) * 32 + lane);
                uint32_t b0 = __float_as_uint(b.x), b1 = __float_as_uint(b.y);
                mma_tf32(c[0][nf], a[0], b0, b1);
                mma_tf32(c[1][nf], a[1], b0, b1);
            }
        }
        __syncthreads();
    }

    // epilogue: * dinv[row], fp16 store
    #pragma unroll
    for (int mf = 0; mf < 2; mf++) {
        int r0 = m0 + wm * 32 + mf * 16 + (lane >> 2);
        int cb = wn * (BN / 2) + (lane & 3) * 2;
        float d0 = (r0 < M)     ? dinv[r0]     : 0.f;
        float d1 = (r0 + 8 < M) ? dinv[r0 + 8] : 0.f;
        #pragma unroll
        for (int nf = 0; nf < NF; nf++) {
            int n = cb + nf * 8;
            if (r0 < M)
                *(__half2*)(C + (size_t)r0 * BN + n) =
                    __floats2half2_rn(c[mf][nf][0] * d0, c[mf][nf][1] * d0);
            if (r0 + 8 < M)
                *(__half2*)(C + (size_t)(r0 + 8) * BN + n) =
                    __floats2half2_rn(c[mf][nf][2] * d1, c[mf][nf][3] * d1);
        }
    }
}

// ---------------- dtype detection (parallel, one warp) -----------------------
__global__ void k_detect(const long long* __restrict__ ei, int E, int N) {
    int lane = threadIdx.x;
    int lim = E < 64 ? E : 64;
    bool bad = false;
    for (int j = lane; j < lim; j += 32) {
        long long v = ei[j];
        if (v < 0 || v >= (long long)N) bad = true;
    }
    unsigned m = __ballot_sync(0xffffffffu, bad);
    if (lane == 0) g_is64 = (m == 0) ? 1 : 0;
}

// ---------------- histogram (reads edge_index directly) ---------------------
__global__ void k_zero(int N) {
    int i = blockIdx.x * blockDim.x + threadIdx.x;
    if (i < N) g_cnt[i] = 0;
}

__global__ void k_hist(const void* __restrict__ ei, int E, int N) {
    int i = blockIdx.x * blockDim.x + threadIdx.x;
    if (i >= E) return;
    int d;
    if (g_is64) d = (int)((const long long*)ei)[i + E];
    else        d = ((const int*)ei)[i + E];
    if (d < 0 || d >= N) d = 0;
    atomicAdd(&g_cnt[d], 1);
}

// ---------------- 3-phase multi-block scan -----------------------------------
__global__ __launch_bounds__(1024) void k_scanA(int N) {
    __shared__ int wsum[32];
    const int lane = threadIdx.x & 31;
    const int wid  = threadIdx.x >> 5;
    const int base = blockIdx.x * SCAN_TILE + threadIdx.x * 4;

    int v0 = 0, v1 = 0, v2 = 0, v3 = 0;
    if (base + 3 < N) {
        v0 = g_cnt[base]; v1 = g_cnt[base + 1];
        v2 = g_cnt[base + 2]; v3 = g_cnt[base + 3];
    } else {
        if (base     < N) v0 = g_cnt[base];
        if (base + 1 < N) v1 = g_cnt[base + 1];
        if (base + 2 < N) v2 = g_cnt[base + 2];
        if (base + 3 < N) v3 = g_cnt[base + 3];
    }
    int p0 = v0, p1 = p0 + v1, p2 = p1 + v2, p3 = p2 + v3;
    int x = p3;
    #pragma unroll
    for (int o = 1; o < 32; o <<= 1) {
        int y = __shfl_up_sync(0xffffffffu, x, o);
        if (lane >= o) x += y;
    }
    if (lane == 31) wsum[wid] = x;
    __syncthreads();
    if (wid == 0) {
        int w = wsum[lane];
        #pragma unroll
        for (int o = 1; o < 32; o <<= 1) {
            int y = __shfl_up_sync(0xffffffffu, w, o);
            if (lane >= o) w += y;
        }
        wsum[lane] = w;
    }
    __syncthreads();
    int texcl = (x - p3) + (wid ? wsum[wid - 1] : 0);
    if (base     < N) g_rowptr[base + 1] = texcl + p0;
    if (base + 1 < N) g_rowptr[base + 2] = texcl + p1;
    if (base + 2 < N) g_rowptr[base + 3] = texcl + p2;
    if (base + 3 < N) g_rowptr[base + 4] = texcl + p3;
    if (threadIdx.x == 1023) g_bsum[blockIdx.x] = wsum[31];
}

__global__ void k_scanB(int nblocks) {
    int lane = threadIdx.x;
    int v = (lane < nblocks) ? g_bsum[lane] : 0;
    int x = v;
    #pragma unroll
    for (int o = 1; o < 32; o <<= 1) {
        int y = __shfl_up_sync(0xffffffffu, x, o);
        if (lane >= o) x += y;
    }
    if (lane < nblocks) g_boff[lane] = x - v;
}

__global__ __launch_bounds__(1024) void k_scanC(int N) {
    int i = blockIdx.x * blockDim.x + threadIdx.x;
    if (i == 0) g_rowptr[0] = 0;
    if (i < N) {
        int incl = g_rowptr[i + 1] + g_boff[i / SCAN_TILE];
        int v = g_cnt[i];
        g_rowptr[i + 1] = incl;
        g_cursor[i]     = incl - v;
        g_dinv[i]       = rsqrtf((float)(v + 1));
    }
}

__global__ void k_scatter(const void* __restrict__ ei, int E, int N) {
    int i = blockIdx.x * blockDim.x + threadIdx.x;
    if (i >= E) return;
    int s, d;
    if (g_is64) {
        const long long* p = (const long long*)ei;
        s = (int)p[i]; d = (int)p[i + E];
    } else {
        const int* p = (const int*)ei;
        s = p[i]; d = p[i + E];
    }
    if (s < 0 || s >= N) s = 0;
    if (d < 0 || d >= N) d = 0;
    int p2 = atomicAdd(&g_cursor[d], 1);
    if (p2 >= 0 && p2 < EMAX) g_csr[p2] = s;
}

// ---------------- layer-1 aggregation + bias + ReLU (F=128, fp16 gather) ----
__global__ __launch_bounds__(256) void k_agg1(const __half* __restrict__ xwh,
                                              const float* __restrict__ bias,
                                              float* __restrict__ out, int N) {
    int node = blockIdx.x * (blockDim.x >> 5) + (threadIdx.x >> 5);
    if (node >= N) return;
    int lane = threadIdx.x & 31;
    float di = g_dinv[node];

    uint2 u = ((const uint2*)(xwh + (size_t)node * 128))[lane];
    float2 q0 = __half22float2(*(const __half2*)&u.x);
    float2 q1 = __half22float2(*(const __half2*)&u.y);
    float4 acc = make_float4(q0.x, q0.y, q1.x, q1.y);

    int e = g_rowptr[node], end = g_rowptr[node + 1];
    for (; e + 1 < end; e += 2) {
        int s0 = g_csr[e], s1 = g_csr[e + 1];
        uint2 a = ((const uint2*)(xwh + (size_t)s0 * 128))[lane];
        uint2 b = ((const uint2*)(xwh + (size_t)s1 * 128))[lane];
        float2 a0 = __half22float2(*(const __half2*)&a.x);
        float2 a1 = __half22float2(*(const __half2*)&a.y);
        float2 b0 = __half22float2(*(const __half2*)&b.x);
        float2 b1 = __half22float2(*(const __half2*)&b.y);
        acc.x += a0.x + b0.x;
        acc.y += a0.y + b0.y;
        acc.z += a1.x + b1.x;
        acc.w += a1.y + b1.y;
    }
    if (e < end) {
        int s = g_csr[e];
        uint2 a = ((const uint2*)(xwh + (size_t)s * 128))[lane];
        float2 a0 = __half22float2(*(const __half2*)&a.x);
        float2 a1 = __half22float2(*(const __half2*)&a.y);
        acc.x += a0.x; acc.y += a0.y; acc.z += a1.x; acc.w += a1.y;
    }
    float4 bb = ((const float4*)bias)[lane];
    float4 r;
    r.x = fmaxf(fmaf(acc.x, di, bb.x), 0.f);
    r.y = fmaxf(fmaf(acc.y, di, bb.y), 0.f);
    r.z = fmaxf(fmaf(acc.z, di, bb.z), 0.f);
    r.w = fmaxf(fmaf(acc.w, di, bb.w), 0.f);
    ((float4*)(out + (size_t)node * 128))[lane] = r;
}

// ---------------- layer-2 aggregation + bias + log_softmax (F=64, fp16) -----
__global__ __launch_bounds__(256) void k_agg2(const __half* __restrict__ xwh,
                                              const float* __restrict__ bias,
                                              float* __restrict__ out, int N) {
    int node = blockIdx.x * (blockDim.x >> 5) + (threadIdx.x >> 5);
    if (node >= N) return;
    int lane = threadIdx.x & 31;
    float di = g_dinv[node];

    unsigned u = ((const unsigned*)(xwh + (size_t)node * 64))[lane];
    float2 acc = __half22float2(*(const __half2*)&u);

    int e = g_rowptr[node], end = g_rowptr[node + 1];
    for (; e + 1 < end; e += 2) {
        int s0 = g_csr[e], s1 = g_csr[e + 1];
        unsigned a = ((const unsigned*)(xwh + (size_t)s0 * 64))[lane];
        unsigned b = ((const unsigned*)(xwh + (size_t)s1 * 64))[lane];
        float2 av = __half22float2(*(const __half2*)&a);
        float2 bv = __half22float2(*(const __half2*)&b);
        acc.x += av.x + bv.x;
        acc.y += av.y + bv.y;
    }
    if (e < end) {
        int s = g_csr[e];
        unsigned a = ((const unsigned*)(xwh + (size_t)s * 64))[lane];
        float2 av = __half22float2(*(const __half2*)&a);
        acc.x += av.x; acc.y += av.y;
    }
    float2 bb = ((const float2*)bias)[lane];
    float vx = fmaf(acc.x, di, bb.x);
    float vy = fmaf(acc.y, di, bb.y);

    float m = fmaxf(vx, vy);
    #pragma unroll
    for (int o = 16; o; o >>= 1) m = fmaxf(m, __shfl_xor_sync(0xffffffffu, m, o));
    float s = expf(vx - m) + expf(vy - m);
    #pragma unroll
    for (int o = 16; o; o >>= 1) s += __shfl_xor_sync(0xffffffffu, s, o);
    float lse = m + logf(s);
    ((float2*)(out + (size_t)node * 64))[lane] = make_float2(vx - lse, vy - lse);
}

// ---------------- launcher ---------------------------------------------------
extern "C" void kernel_launch(void* const* d_in, const int* in_sizes, int n_in,
                              void* d_out, int out_size) {
    const float* x   = (const float*)d_in[0];
    const void*  ei  = d_in[1];
    const float* W1  = (const float*)d_in[2];
    const float* b1  = (const float*)d_in[3];
    const float* W2  = (const float*)d_in[4];
    const float* b2  = (const float*)d_in[5];
    float*       out = (float*)d_out;

    const int N = in_sizes[0] / 128;
    const int E = in_sizes[1] / 2;
    const int nScanBlocks = (N + SCAN_TILE - 1) / SCAN_TILE;

    __half *xw1h, *xw2h;
    float *h, *bf1, *bf2, *dinv;
    cudaGetSymbolAddress((void**)&xw1h, g_xw1h);
    cudaGetSymbolAddress((void**)&h,    g_h);
    cudaGetSymbolAddress((void**)&xw2h, g_xw2h);
    cudaGetSymbolAddress((void**)&bf1,  g_bf1);
    cudaGetSymbolAddress((void**)&bf2,  g_bf2);
    cudaGetSymbolAddress((void**)&dinv, g_dinv);

    // W fragment prep
    k_bfrag<<<(16 * 16 * 64 + 16 * 8 * 64 + 255) / 256, 256>>>(W1, W2);

    // CSR build (dtype-robust, parallel scan, direct edge_index reads)
    k_detect <<<1, 32>>>((const long long*)ei, E, N);
    k_zero   <<<(N + 255) / 256, 256>>>(N);
    k_hist   <<<(E + 255) / 256, 256>>>(ei, E, N);
    k_scanA  <<<nScanBlocks, 1024>>>(N);
    k_scanB  <<<1, 32>>>(nScanBlocks);
    k_scanC  <<<(N + 1023) / 1024, 1024>>>(N);
    k_scatter<<<(E + 255) / 256, 256>>>(ei, E, N);

    const int gBlocks = (N + 127) / 128;

    // Layer 1: xw1h = (x @ W1)*dinv (tf32 TC, fp16 out) ; h = relu(agg + b1)
    k_gemm_tc<128><<<gBlocks, 256>>>(x, bf1, xw1h, dinv, N);
    k_agg1<<<(N + 7) / 8, 256>>>(xw1h, b1, h, N);

    // Layer 2: xw2h = (h @ W2)*dinv ; out = log_softmax(agg + b2)
    k_gemm_tc<64><<<gBlocks, 256>>>(h, bf2, xw2h, dinv, N);
    k_agg2<<<(N + 7) / 8, 256>>>(xw2h, b2, out, N);
}

// round 12
// speedup vs baseline: 2.5290x; 1.0443x over previous
#include <cuda_runtime.h>
#include <cuda_fp16.h>
#include <math.h>
#include <stdint.h>

// ---------------- problem-size scratch (device globals: allocation-free) ----
#define NMAX 100000
#define EMAX 1600000
#define SCAN_TILE 4096
#define MAX_SCAN_BLOCKS ((NMAX + SCAN_TILE - 1) / SCAN_TILE)
#define BFRAG1 (16 * 16 * 64)
#define BFRAG2 (16 * 8 * 64)

__device__ __half g_xw1h[NMAX * 128]; // (x @ W1) * dinv[row], fp16
__device__ float  g_h   [NMAX * 128]; // layer-1 output (post agg+bias+relu)
__device__ __half g_xw2h[NMAX * 64];  // (h @ W2) * dinv[row], fp16
__device__ float  g_dinv[NMAX];       // rsqrt(in_degree + 1)
__device__ int    g_cnt[NMAX];
__device__ int    g_rowptr[NMAX + 1];
__device__ int    g_cursor[NMAX];
__device__ int    g_csr[EMAX];
__device__ int    g_is64;
// packed lookback tile state: bits[63:62] = {0 invalid, 1 aggregate, 2 inclusive},
// bits[31:0] = value. Single 8-byte word -> flag+value read atomically.
__device__ unsigned long long g_tile[MAX_SCAN_BLOCKS];
__device__ float  g_bf1[BFRAG1];      // W1 mma fragments
__device__ float  g_bf2[BFRAG2];      // W2 mma fragments

// ---------------- mma helpers ------------------------------------------------
__device__ __forceinline__ float cvt_tf32(float x) {
    uint32_t r; asm("cvt.rna.tf32.f32 %0, %1;" : "=r"(r) : "f"(x));
    return __uint_as_float(r);
}
__device__ __forceinline__ uint32_t smem_u32(const void* p) {
    return (uint32_t)__cvta_generic_to_shared(p);
}
__device__ __forceinline__ void ldsm4(uint32_t& r0, uint32_t& r1, uint32_t& r2,
                                      uint32_t& r3, uint32_t a) {
    asm volatile("ldmatrix.sync.aligned.m8n8.x4.shared.b16 {%0,%1,%2,%3}, [%4];"
                 : "=r"(r0), "=r"(r1), "=r"(r2), "=r"(r3) : "r"(a));
}
__device__ __forceinline__ void mma_tf32(float c[4], const uint32_t a[4],
                                         uint32_t b0, uint32_t b1) {
    asm volatile("mma.sync.aligned.m16n8k8.row.col.f32.tf32.tf32.f32 "
                 "{%0,%1,%2,%3}, {%4,%5,%6,%7}, {%8,%9}, {%0,%1,%2,%3};"
                 : "+f"(c[0]), "+f"(c[1]), "+f"(c[2]), "+f"(c[3])
                 : "r"(a[0]), "r"(a[1]), "r"(a[2]), "r"(a[3]), "r"(b0), "r"(b1));
}

// ---------------- fused init: zero cnt + bfrag + detect + tile reset ---------
__global__ void k_init(const float* __restrict__ W1, const float* __restrict__ W2,
                       const long long* __restrict__ ei, int E, int N) {
    int t = blockIdx.x * blockDim.x + threadIdx.x;
    if (t < N) g_cnt[t] = 0;
    if (t < MAX_SCAN_BLOCKS) *((volatile unsigned long long*)&g_tile[t]) = 0ull;
    if (t < BFRAG1) {
        int j    = t & 1;
        int lane = (t >> 1) & 31;
        int nf   = (t >> 6) & 15;
        int ks   = t >> 10;
        int k = ks * 8 + (lane & 3) + j * 4;
        int n = nf * 8 + (lane >> 2);
        g_bf1[t] = cvt_tf32(W1[k * 128 + n]);
    } else if (t < BFRAG1 + BFRAG2) {
        int u = t - BFRAG1;
        int j    = u & 1;
        int lane = (u >> 1) & 31;
        int nf   = (u >> 6) & 7;
        int ks   = u >> 9;
        int k = ks * 8 + (lane & 3) + j * 4;
        int n = nf * 8 + (lane >> 2);
        g_bf2[u] = cvt_tf32(W2[k * 64 + n]);
    }
    if (blockIdx.x == 0 && threadIdx.x < 32) {
        int lane = threadIdx.x;
        int lim = E < 64 ? E : 64;
        bool bad = false;
        for (int j = lane; j < lim; j += 32) {
            long long v = ei[j];
            if (v < 0 || v >= (long long)N) bad = true;
        }
        unsigned m = __ballot_sync(0xffffffffu, bad);
        if (lane == 0) g_is64 = (m == 0) ? 1 : 0;
    }
}

// ---------------- histogram (2 edges/thread, vectorized) ---------------------
__global__ void k_hist(const void* __restrict__ ei, int E, int N) {
    int i = (blockIdx.x * blockDim.x + threadIdx.x) * 2;
    if (i >= E) return;
    int d0, d1 = -1;
    if (g_is64) {
        const long long* p = (const long long*)ei + E;
        if (i + 1 < E) {
            longlong2 v = *(const longlong2*)(p + i);
            d0 = (int)v.x; d1 = (int)v.y;
        } else d0 = (int)p[i];
    } else {
        const int* p = (const int*)ei + E;
        if (i + 1 < E) {
            int2 v = *(const int2*)(p + i);
            d0 = v.x; d1 = v.y;
        } else d0 = p[i];
    }
    if (d0 < 0 || d0 >= N) d0 = 0;
    if (i + 1 < E) {
        if (d1 < 0 || d1 >= N) d1 = 0;
        if (d1 == d0) { atomicAdd(&g_cnt[d0], 2); return; }
        atomicAdd(&g_cnt[d1], 1);
    }
    atomicAdd(&g_cnt[d0], 1);
}

// ---------------- single-pass scan (packed-word decoupled lookback) ----------
__global__ __launch_bounds__(1024) void k_scan(int N) {
    __shared__ int wsum[32];
    __shared__ int s_off;
    const int lane = threadIdx.x & 31;
    const int wid  = threadIdx.x >> 5;
    const int bid  = blockIdx.x;
    const int base = bid * SCAN_TILE + threadIdx.x * 4;

    int v0 = 0, v1 = 0, v2 = 0, v3 = 0;
    if (base + 3 < N) {
        v0 = g_cnt[base]; v1 = g_cnt[base + 1];
        v2 = g_cnt[base + 2]; v3 = g_cnt[base + 3];
    } else {
        if (base     < N) v0 = g_cnt[base];
        if (base + 1 < N) v1 = g_cnt[base + 1];
        if (base + 2 < N) v2 = g_cnt[base + 2];
        if (base + 3 < N) v3 = g_cnt[base + 3];
    }
    int p0 = v0, p1 = p0 + v1, p2 = p1 + v2, p3 = p2 + v3;
    int x = p3;
    #pragma unroll
    for (int o = 1; o < 32; o <<= 1) {
        int y = __shfl_up_sync(0xffffffffu, x, o);
        if (lane >= o) x += y;
    }
    if (lane == 31) wsum[wid] = x;
    __syncthreads();
    if (wid == 0) {
        int w = wsum[lane];
        #pragma unroll
        for (int o = 1; o < 32; o <<= 1) {
            int y = __shfl_up_sync(0xffffffffu, w, o);
            if (lane >= o) w += y;
        }
        wsum[lane] = w;
    }
    __syncthreads();
    int texcl = (x - p3) + (wid ? wsum[wid - 1] : 0);
    int btotal = wsum[31];

    if (threadIdx.x == 0) {
        volatile unsigned long long* tile = (volatile unsigned long long*)g_tile;
        if (bid == 0) {
            tile[0] = (2ull << 62) | (unsigned int)btotal;   // inclusive
            s_off = 0;
        } else {
            tile[bid] = (1ull << 62) | (unsigned int)btotal; // aggregate
            int off = 0;
            for (int p = bid - 1; p >= 0; p--) {
                unsigned long long tv;
                do { tv = tile[p]; } while ((tv >> 62) == 0);
                off += (int)(unsigned int)(tv & 0xffffffffull);
                if ((tv >> 62) == 2) break;
            }
            tile[bid] = (2ull << 62) | (unsigned int)(off + btotal);
            s_off = off;
        }
    }
    __syncthreads();
    int off = s_off;
    if (bid == 0 && threadIdx.x == 0) g_rowptr[0] = 0;
    if (base < N) {
        int incl = off + texcl + p0;
        g_rowptr[base + 1] = incl;
        g_cursor[base]     = incl - v0;
        g_dinv[base]       = rsqrtf((float)(v0 + 1));
    }
    if (base + 1 < N) {
        int incl = off + texcl + p1;
        g_rowptr[base + 2] = incl;
        g_cursor[base + 1] = incl - v1;
        g_dinv[base + 1]   = rsqrtf((float)(v1 + 1));
    }
    if (base + 2 < N) {
        int incl = off + texcl + p2;
        g_rowptr[base + 3] = incl;
        g_cursor[base + 2] = incl - v2;
        g_dinv[base + 2]   = rsqrtf((float)(v2 + 1));
    }
    if (base + 3 < N) {
        int incl = off + texcl + p3;
        g_rowptr[base + 4] = incl;
        g_cursor[base + 3] = incl - v3;
        g_dinv[base + 3]   = rsqrtf((float)(v3 + 1));
    }
}

// ---------------- scatter (2 edges/thread, vectorized reads) -----------------
__global__ void k_scatter(const void* __restrict__ ei, int E, int N) {
    int i = (blockIdx.x * blockDim.x + threadIdx.x) * 2;
    if (i >= E) return;
    int s0, d0, s1 = -1, d1 = -1;
    bool two = (i + 1 < E);
    if (g_is64) {
        const long long* ps = (const long long*)ei;
        const long long* pd = ps + E;
        if (two) {
            longlong2 vs = *(const longlong2*)(ps + i);
            longlong2 vd = *(const longlong2*)(pd + i);
            s0 = (int)vs.x; s1 = (int)vs.y; d0 = (int)vd.x; d1 = (int)vd.y;
        } else { s0 = (int)ps[i]; d0 = (int)pd[i]; }
    } else {
        const int* ps = (const int*)ei;
        const int* pd = ps + E;
        if (two) {
            int2 vs = *(const int2*)(ps + i);
            int2 vd = *(const int2*)(pd + i);
            s0 = vs.x; s1 = vs.y; d0 = vd.x; d1 = vd.y;
        } else { s0 = ps[i]; d0 = pd[i]; }
    }
    if (s0 < 0 || s0 >= N) s0 = 0;
    if (d0 < 0 || d0 >= N) d0 = 0;
    int p0 = atomicAdd(&g_cursor[d0], 1);
    if (p0 >= 0 && p0 < EMAX) g_csr[p0] = s0;
    if (two) {
        if (s1 < 0 || s1 >= N) s1 = 0;
        if (d1 < 0 || d1 >= N) d1 = 0;
        int p1 = atomicAdd(&g_cursor[d1], 1);
        if (p1 >= 0 && p1 < EMAX) g_csr[p1] = s1;
    }
}

// ---------------- tensor-core GEMM: Ch[M,BN] = (A[M,128] @ W) * dinv, fp16 --
template <int BN>
__global__ __launch_bounds__(256, 2) void k_gemm_tc(const float* __restrict__ A,
                                                    const float* __restrict__ BF,
                                                    __half* __restrict__ C,
                                                    const float* __restrict__ dinv,
                                                    int M) {
    constexpr int NFTOT = BN / 8;
    constexpr int NF    = NFTOT / 2;
    constexpr int LDA   = 68;
    __shared__ float As[128 * LDA];

    const int tid  = threadIdx.x;
    const int lane = tid & 31;
    const int wid  = tid >> 5;
    const int wm   = wid & 3;
    const int wn   = wid >> 2;
    const int m0   = blockIdx.x * 128;

    float c[2][NF][4];
    #pragma unroll
    for (int mf = 0; mf < 2; mf++)
        #pragma unroll
        for (int nf = 0; nf < NF; nf++)
            #pragma unroll
            for (int i = 0; i < 4; i++) c[mf][nf][i] = 0.f;

    const uint32_t a_base =
        smem_u32(As) + (((wm * 32 + (lane & 15)) * LDA + (lane >> 4) * 4) << 2);

    #pragma unroll
    for (int half_ = 0; half_ < 2; half_++) {
        #pragma unroll
        for (int it = 0; it < 8; it++) {
            int r  = (tid >> 4) + it * 16;
            int q  = tid & 15;
            int gm = m0 + r;
            float4 v = make_float4(0.f, 0.f, 0.f, 0.f);
            if (gm < M)
                v = *(const float4*)(A + (size_t)gm * 128 + half_ * 64 + q * 4);
            v.x = cvt_tf32(v.x); v.y = cvt_tf32(v.y);
            v.z = cvt_tf32(v.z); v.w = cvt_tf32(v.w);
            *(float4*)(As + r * LDA + q * 4) = v;
        }
        __syncthreads();

        #pragma unroll
        for (int ks = 0; ks < 8; ks++) {
            uint32_t a[2][4];
            #pragma unroll
            for (int mf = 0; mf < 2; mf++)
                ldsm4(a[mf][0], a[mf][1], a[mf][2], a[mf][3],
                      a_base + mf * (16 * LDA * 4) + ks * 32);
            int ksg = half_ * 8 + ks;
            #pragma unroll
            for (int nf = 0; nf < NF; nf++) {
                float2 b = __ldg((const float2*)BF +
                                 (size_t)(ksg * NFTOT + wn * NF + nf) * 32 + lane);
                uint32_t b0 = __float_as_uint(b.x), b1 = __float_as_uint(b.y);
                mma_tf32(c[0][nf], a[0], b0, b1);
                mma_tf32(c[1][nf], a[1], b0, b1);
            }
        }
        __syncthreads();
    }

    #pragma unroll
    for (int mf = 0; mf < 2; mf++) {
        int r0 = m0 + wm * 32 + mf * 16 + (lane >> 2);
        int cb = wn * (BN / 2) + (lane & 3) * 2;
        float d0 = (r0 < M)     ? dinv[r0]     : 0.f;
        float d1 = (r0 + 8 < M) ? dinv[r0 + 8] : 0.f;
        #pragma unroll
        for (int nf = 0; nf < NF; nf++) {
            int n = cb + nf * 8;
            if (r0 < M)
                *(__half2*)(C + (size_t)r0 * BN + n) =
                    __floats2half2_rn(c[mf][nf][0] * d0, c[mf][nf][1] * d0);
            if (r0 + 8 < M)
                *(__half2*)(C + (size_t)(r0 + 8) * BN + n) =
                    __floats2half2_rn(c[mf][nf][2] * d1, c[mf][nf][3] * d1);
        }
    }
}

// ---------------- layer-1 aggregation + bias + ReLU (F=128, fp16 gather) ----
__global__ __launch_bounds__(256) void k_agg1(const __half* __restrict__ xwh,
                                              const float* __restrict__ bias,
                                              float* __restrict__ out, int N, int E) {
    int node = blockIdx.x * (blockDim.x >> 5) + (threadIdx.x >> 5);
    if (node >= N) return;
    int lane = threadIdx.x & 31;
    float di = g_dinv[node];

    uint2 u = ((const uint2*)(xwh + (size_t)node * 128))[lane];
    float2 q0 = __half22float2(*(const __half2*)&u.x);
    float2 q1 = __half22float2(*(const __half2*)&u.y);
    float4 acc = make_float4(q0.x, q0.y, q1.x, q1.y);

    int e = g_rowptr[node], end = g_rowptr[node + 1];
    if (e < 0) e = 0;
    if (end > E) end = E;                 // hard safety clamp
    for (; e + 1 < end; e += 2) {
        int s0 = g_csr[e], s1 = g_csr[e + 1];
        uint2 a = ((const uint2*)(xwh + (size_t)s0 * 128))[lane];
        uint2 b = ((const uint2*)(xwh + (size_t)s1 * 128))[lane];
        float2 a0 = __half22float2(*(const __half2*)&a.x);
        float2 a1 = __half22float2(*(const __half2*)&a.y);
        float2 b0 = __half22float2(*(const __half2*)&b.x);
        float2 b1 = __half22float2(*(const __half2*)&b.y);
        acc.x += a0.x + b0.x;
        acc.y += a0.y + b0.y;
        acc.z += a1.x + b1.x;
        acc.w += a1.y + b1.y;
    }
    if (e < end) {
        int s = g_csr[e];
        uint2 a = ((const uint2*)(xwh + (size_t)s * 128))[lane];
        float2 a0 = __half22float2(*(const __half2*)&a.x);
        float2 a1 = __half22float2(*(const __half2*)&a.y);
        acc.x += a0.x; acc.y += a0.y; acc.z += a1.x; acc.w += a1.y;
    }
    float4 bb = ((const float4*)bias)[lane];
    float4 r;
    r.x = fmaxf(fmaf(acc.x, di, bb.x), 0.f);
    r.y = fmaxf(fmaf(acc.y, di, bb.y), 0.f);
    r.z = fmaxf(fmaf(acc.z, di, bb.z), 0.f);
    r.w = fmaxf(fmaf(acc.w, di, bb.w), 0.f);
    ((float4*)(out + (size_t)node * 128))[lane] = r;
}

// ---------------- layer-2 aggregation + bias + log_softmax (F=64, fp16) -----
__global__ __launch_bounds__(256) void k_agg2(const __half* __restrict__ xwh,
                                              const float* __restrict__ bias,
                                              float* __restrict__ out, int N, int E) {
    int node = blockIdx.x * (blockDim.x >> 5) + (threadIdx.x >> 5);
    if (node >= N) return;
    int lane = threadIdx.x & 31;
    float di = g_dinv[node];

    unsigned u = ((const unsigned*)(xwh + (size_t)node * 64))[lane];
    float2 acc = __half22float2(*(const __half2*)&u);

    int e = g_rowptr[node], end = g_rowptr[node + 1];
    if (e < 0) e = 0;
    if (end > E) end = E;                 // hard safety clamp
    for (; e + 1 < end; e += 2) {
        int s0 = g_csr[e], s1 = g_csr[e + 1];
        unsigned a = ((const unsigned*)(xwh + (size_t)s0 * 64))[lane];
        unsigned b = ((const unsigned*)(xwh + (size_t)s1 * 64))[lane];
        float2 av = __half22float2(*(const __half2*)&a);
        float2 bv = __half22float2(*(const __half2*)&b);
        acc.x += av.x + bv.x;
        acc.y += av.y + bv.y;
    }
    if (e < end) {
        int s = g_csr[e];
        unsigned a = ((const unsigned*)(xwh + (size_t)s * 64))[lane];
        float2 av = __half22float2(*(const __half2*)&a);
        acc.x += av.x; acc.y += av.y;
    }
    float2 bb = ((const float2*)bias)[lane];
    float vx = fmaf(acc.x, di, bb.x);
    float vy = fmaf(acc.y, di, bb.y);

    float m = fmaxf(vx, vy);
    #pragma unroll
    for (int o = 16; o; o >>= 1) m = fmaxf(m, __shfl_xor_sync(0xffffffffu, m, o));
    float s = expf(vx - m) + expf(vy - m);
    #pragma unroll
    for (int o = 16; o; o >>= 1) s += __shfl_xor_sync(0xffffffffu, s, o);
    float lse = m + logf(s);
    ((float2*)(out + (size_t)node * 64))[lane] = make_float2(vx - lse, vy - lse);
}

// ---------------- launcher ---------------------------------------------------
extern "C" void kernel_launch(void* const* d_in, const int* in_sizes, int n_in,
                              void* d_out, int out_size) {
    const float* x   = (const float*)d_in[0];
    const void*  ei  = d_in[1];
    const float* W1  = (const float*)d_in[2];
    const float* b1  = (const float*)d_in[3];
    const float* W2  = (const float*)d_in[4];
    const float* b2  = (const float*)d_in[5];
    float*       out = (float*)d_out;

    const int N = in_sizes[0] / 128;
    const int E = in_sizes[1] / 2;
    const int nScanBlocks = (N + SCAN_TILE - 1) / SCAN_TILE;

    __half *xw1h, *xw2h;
    float *h, *bf1, *bf2, *dinv;
    cudaGetSymbolAddress((void**)&xw1h, g_xw1h);
    cudaGetSymbolAddress((void**)&h,    g_h);
    cudaGetSymbolAddress((void**)&xw2h, g_xw2h);
    cudaGetSymbolAddress((void**)&bf1,  g_bf1);
    cudaGetSymbolAddress((void**)&bf2,  g_bf2);
    cudaGetSymbolAddress((void**)&dinv, g_dinv);

    // side stream + events: created once on the (uncaptured) correctness call
    static cudaStream_t s2 = nullptr;
    static cudaEvent_t ev1 = nullptr, ev2 = nullptr;
    if (s2 == nullptr) {
        cudaStreamCreateWithFlags(&s2, cudaStreamNonBlocking);
        cudaEventCreateWithFlags(&ev1, cudaEventDisableTiming);
        cudaEventCreateWithFlags(&ev2, cudaEventDisableTiming);
    }

    const int initThreads = (N > BFRAG1 + BFRAG2) ? N : (BFRAG1 + BFRAG2);
    const int eThreads2   = (E + 1) / 2;
    const int gBlocks     = (N + 127) / 128;

    // CSR build prologue (main stream)
    k_init<<<(initThreads + 255) / 256, 256>>>(W1, W2, (const long long*)ei, E, N);
    k_hist<<<(eThreads2 + 255) / 256, 256>>>(ei, E, N);
    k_scan<<<nScanBlocks, 1024>>>(N);

    // fork: gemm1 needs only bfrag + dinv -> run on side stream over scatter
    cudaEventRecord(ev1, 0);
    cudaStreamWaitEvent(s2, ev1, 0);
    k_gemm_tc<128><<<gBlocks, 256, 0, s2>>>(x, bf1, xw1h, dinv, N);
    cudaEventRecord(ev2, s2);

    k_scatter<<<(eThreads2 + 255) / 256, 256>>>(ei, E, N);

    // join, then the dependent tail
    cudaStreamWaitEvent(0, ev2, 0);
    k_agg1<<<(N + 7) / 8, 256>>>(xw1h, b1, h, N, E);
    k_gemm_tc<64><<<gBlocks, 256>>>(h, bf2, xw2h, dinv, N);
    k_agg2<<<(N + 7) / 8, 256>>>(xw2h, b2, out, N, E);
}